// round 6
// baseline (speedup 1.0000x reference)
#include <cuda_runtime.h>

// PLNet expansion: out[pp][n,k,i,j,y,x] =
//   0.5*cor0[ij]*cork[ij] * cen0[yx]*cenk[yx]
//   * cor[23+y][ij]*cor[37+x][ij] * cen[23+i][yx]*cen[37+j][yx]
// cor = corner(pp&1), cen = center(pp>>1). Input (n,204,14,14).
//
// Block: (k-pair {bx, bx+10}, n=by, i-chunk {2bz, 2bz+1}), 196 threads
// = 4 pp x 49 quads. Each inner iteration emits TWO STG.128 (k and k+10)
// from 4 LDS: Wd float2 tables (a-folded, per k) + V float2 loads.

__global__ __launch_bounds__(196)
void plnet_kernel(const float* __restrict__ in, float* __restrict__ out)
{
    const int k  = blockIdx.x;        // 0..9 -> output k and k+10
    const int n  = blockIdx.y;        // 0..31
    const int i0 = blockIdx.z * 2;    // 0,2,...,12
    const int t  = threadIdx.x;

    // Wd[cc][kk][rij][y] = a * (cor[23+y], cor[24+y])   (y 0..13, pad 15)
    // V[cc][rij][x]      = cor[37+x]
    __shared__ float2 Wd_s[2][2][28][15];
    __shared__ float  V_s[2][28][14];
    __shared__ float  a_s[2][2][28];

    const float* nb = in + n * (204 * 196);

    // a = 0.5*cor0*cork per (cc, kk, rij)
    if (t < 112) {
        const int cc  = t / 56;
        const int r   = t - cc * 56;
        const int kk  = r / 28;
        const int rij = r - kk * 28;
        const int ij  = i0 * 14 + rij;
        const float* cor = nb + cc * (51 * 196);
        a_s[cc][kk][rij] = 0.5f * cor[ij] * cor[(1 + k + 10 * kk) * 196 + ij];
    }
    __syncthreads();

    // V build: 2cc x 28rij x 14x = 784 items, rij fastest (coalesced LDG)
    #pragma unroll
    for (int p = 0; p < 784; p += 196) {
        const int id  = p + t;
        const int rij = id % 28;
        const int tmp = id / 28;       // 0..27
        const int x   = tmp % 14;
        const int cc  = tmp / 14;
        const int ij  = i0 * 14 + rij;
        V_s[cc][rij][x] = nb[cc * (51 * 196) + (37 + x) * 196 + ij];
    }
    // Wd build: 2cc x 2kk x 28rij x 14y = 1568 items
    #pragma unroll
    for (int p = 0; p < 1568; p += 196) {
        const int id  = p + t;
        const int rij = id % 28;
        const int tmp = id / 28;       // 0..55
        const int y   = tmp % 14;
        const int t2  = tmp / 14;      // 0..3  = kk + 2*cc
        const int kk  = t2 & 1;
        const int cc  = t2 >> 1;
        const int ij  = i0 * 14 + rij;
        const float* cor = nb + cc * (51 * 196);
        const float a  = a_s[cc][kk][rij];
        Wd_s[cc][kk][rij][y] = make_float2(a * cor[(23 + y) * 196 + ij],
                                           a * cor[(24 + y) * 196 + ij]);
    }

    // per-thread setup
    const int pp = t / 49;
    const int q  = t - pp * 49;
    const int cc = pp & 1;
    const int ss = pp >> 1;
    const int e0 = q * 4;             // plane base (y*14+x), 16B aligned
    const int y0 = e0 / 14;
    const int x0 = e0 - y0 * 14;      // even, 0..12
    const bool cross = (x0 == 12);    // elems 2,3 wrap to (y0+1, x=0,1)
    const int vxo = cross ? 0 : x0 + 2;

    const float* cen = nb + (102 + ss * 51) * 196;
    const float4 c0  = *(const float4*)(cen + e0);
    const float4 ck1 = *(const float4*)(cen + (1 + k) * 196 + e0);
    const float4 ck2 = *(const float4*)(cen + (11 + k) * 196 + e0);
    const float b0a = c0.x * ck1.x, b1a = c0.y * ck1.y, b2a = c0.z * ck1.z, b3a = c0.w * ck1.w;
    const float b0b = c0.x * ck2.x, b1b = c0.y * ck2.y, b2b = c0.z * ck2.z, b3b = c0.w * ck2.w;

    __syncthreads();

    float* op1 = out + (size_t)((pp * 32 + n) * 20 + k) * 38416
                     + (size_t)i0 * 2744 + e0;
    float* op2 = op1 + (size_t)10 * 38416;

    const float2 (*Wc1)[15] = Wd_s[cc][0];
    const float2 (*Wc2)[15] = Wd_s[cc][1];
    const float  (*Vc)[14]  = V_s[cc];

    #pragma unroll
    for (int jb = 0; jb < 14; jb += 7) {
        float4 L[7];
        #pragma unroll
        for (int j = 0; j < 7; ++j)
            L[j] = *(const float4*)(cen + (37 + jb + j) * 196 + e0);

        #pragma unroll
        for (int il = 0; il < 2; ++il) {
            const float4 sx = *(const float4*)(cen + (23 + i0 + il) * 196 + e0);
            const float r0a = b0a * sx.x, r1a = b1a * sx.y, r2a = b2a * sx.z, r3a = b3a * sx.w;
            const float r0b = b0b * sx.x, r1b = b1b * sx.y, r2b = b2b * sx.z, r3b = b3b * sx.w;

            const int rij0 = il * 14 + jb;
            float* o1 = op1 + (size_t)il * 2744 + (size_t)jb * 196;
            float* o2 = op2 + (size_t)il * 2744 + (size_t)jb * 196;

            #pragma unroll
            for (int j = 0; j < 7; ++j) {
                const float2 w1 = Wc1[rij0 + j][y0];
                const float2 w2 = Wc2[rij0 + j][y0];
                const float wlo1 = w1.x, whi1 = cross ? w1.y : w1.x;
                const float wlo2 = w2.x, whi2 = cross ? w2.y : w2.x;
                const float* vr = Vc[rij0 + j];
                const float2 vA = *(const float2*)(vr + x0);
                const float2 vB = *(const float2*)(vr + vxo);

                const float g0 = r0a * L[j].x, g1 = r1a * L[j].y;
                const float g2 = r2a * L[j].z, g3 = r3a * L[j].w;
                const float h0 = r0b * L[j].x, h1 = r1b * L[j].y;
                const float h2 = r2b * L[j].z, h3 = r3b * L[j].w;

                float4 oA;
                oA.x = (wlo1 * vA.x) * g0;
                oA.y = (wlo1 * vA.y) * g1;
                oA.z = (whi1 * vB.x) * g2;
                oA.w = (whi1 * vB.y) * g3;
                *(float4*)(o1 + j * 196) = oA;

                float4 oB;
                oB.x = (wlo2 * vA.x) * h0;
                oB.y = (wlo2 * vA.y) * h1;
                oB.z = (whi2 * vB.x) * h2;
                oB.w = (whi2 * vB.y) * h3;
                *(float4*)(o2 + j * 196) = oB;
            }
        }
    }
}

extern "C" void kernel_launch(void* const* d_in, const int* in_sizes, int n_in,
                              void* d_out, int out_size)
{
    const float* in = (const float*)d_in[0];
    float* out = (float*)d_out;
    dim3 grid(10, 32, 7);
    plnet_kernel<<<grid, 196>>>(in, out);
}

// round 7
// speedup vs baseline: 1.1557x; 1.1557x over previous
#include <cuda_runtime.h>

// PLNet expansion: out[pp][n,k,i,j,y,x] =
//   0.5*cor0[ij]*cork[ij] * cen0[yx]*cenk[yx]
//   * cor[23+y][ij] * cor[37+x][ij] * cen[23+i][yx] * cen[37+j][yx]
// cor = corner(pp&1), cen = center(pp>>1).
// Input (n, 204, 14, 14): corner1 ch 0..50, corner2 51..101,
// center1 102..152, center2 153..203.
//
// R4 structure (best: 72.0 us ncu) + ONE change: __stcs evict-first stores.
// Block (k=bx, n=by, ichunk=bz -> i in {2bz, 2bz+1}), 196 threads.
// Thread t: pp = t/49, q = t%49 (aligned float4 quad of the (y,x) plane).

__global__ __launch_bounds__(196)
void plnet_kernel(const float* __restrict__ in, float* __restrict__ out)
{
    const int k  = blockIdx.x;      // 0..19
    const int n  = blockIdx.y;      // 0..31
    const int i0 = blockIdx.z * 2;  // 0,2,...,12
    const int t  = threadIdx.x;

    // W[cc][rij][y] = 0.5*cor0*cork*cor[23+y] ; V[cc][rij][x] = cor[37+x]
    __shared__ float W_s[2 * 28 * 14];
    __shared__ float V_s[2 * 28 * 14];
    __shared__ float a_s[2 * 28];

    const float* nb = in + n * (204 * 196);

    if (t < 56) {
        const int cc  = t / 28;
        const int rij = t - cc * 28;
        const int ij  = i0 * 14 + rij;
        const float* cor = nb + cc * (51 * 196);
        a_s[t] = 0.5f * cor[ij] * cor[(1 + k) * 196 + ij];
    }
    __syncthreads();

    #pragma unroll
    for (int idx = 0; idx < 784; idx += 196) {
        const int id  = idx + t;
        const int rij = id % 28;
        const int tmp = id / 28;
        const int y   = tmp % 14;
        const int cc  = tmp / 14;
        const int ij  = i0 * 14 + rij;
        const float* cor = nb + cc * (51 * 196);
        W_s[cc * 392 + rij * 14 + y] = a_s[cc * 28 + rij] * cor[(23 + y) * 196 + ij];
        V_s[cc * 392 + rij * 14 + y] = cor[(37 + y) * 196 + ij];
    }

    const int pp = t / 49;
    const int q  = t - pp * 49;
    const int cc = pp & 1;
    const int ss = pp >> 1;
    const int e0 = q * 4;           // plane base (y*14+x), 16B aligned
    const int y0 = e0 / 14;
    const int x0 = e0 - y0 * 14;    // even, 0..12

    const float* cen = nb + (102 + ss * 51) * 196;

    const float4 c0 = *(const float4*)(cen + e0);
    const float4 ck = *(const float4*)(cen + (1 + k) * 196 + e0);
    const float bx = c0.x * ck.x, by = c0.y * ck.y, bz = c0.z * ck.z, bw = c0.w * ck.w;

    const bool cross = (x0 == 12);  // elems 2,3 wrap to (y0+1, x=0,1)
    const int vxo = cross ? 0 : x0 + 2;
    const int y1  = cross ? y0 + 1 : y0;

    __syncthreads();

    float* op = out + (size_t)((pp * 32 + n) * 20 + k) * 38416
                    + (size_t)i0 * (14 * 196) + e0;
    const float* Wc = W_s + cc * 392;
    const float* Vc = V_s + cc * 392;

    #pragma unroll
    for (int jb = 0; jb < 14; jb += 7) {
        float4 L[7];
        #pragma unroll
        for (int j = 0; j < 7; ++j)
            L[j] = *(const float4*)(cen + (37 + jb + j) * 196 + e0);

        #pragma unroll
        for (int il = 0; il < 2; ++il) {
            const int i = i0 + il;
            const float4 sx = *(const float4*)(cen + (23 + i) * 196 + e0);
            const float r0 = bx * sx.x, r1 = by * sx.y, r2 = bz * sx.z, r3 = bw * sx.w;

            const float* Wr = Wc + il * 196;
            const float* Vr = Vc + il * 196;
            float* orow = op + (size_t)il * (14 * 196) + (size_t)jb * 196;

            #pragma unroll
            for (int j = 0; j < 7; ++j) {
                const float* wr = Wr + (jb + j) * 14;
                const float* vr = Vr + (jb + j) * 14;
                const float wlo = wr[y0];
                const float whi = wr[y1];
                const float2 vA = *(const float2*)(vr + x0);
                const float2 vB = *(const float2*)(vr + vxo);
                float4 o;
                o.x = (wlo * vA.x) * (r0 * L[j].x);
                o.y = (wlo * vA.y) * (r1 * L[j].y);
                o.z = (whi * vB.x) * (r2 * L[j].z);
                o.w = (whi * vB.y) * (r3 * L[j].w);
                __stcs((float4*)(orow + j * 196), o);
            }
        }
    }
}

extern "C" void kernel_launch(void* const* d_in, const int* in_sizes, int n_in,
                              void* d_out, int out_size)
{
    const float* in = (const float*)d_in[0];
    float* out = (float*)d_out;
    dim3 grid(20, 32, 7);
    plnet_kernel<<<grid, 196>>>(in, out);
}